// round 13
// baseline (speedup 1.0000x reference)
#include <cuda_runtime.h>
#include <math.h>

// ---------------------------------------------------------------------------
// GRAPEIso: conv3x3(3->1024) + pixel_shuffle(4) + pixel_unshuffle(2) + head
// algebraically folded into a 96-output 3x3 conv, then Gaussian splatting
// with exclusive shared-memory image tiles (scatter + smem atomics).
// R13: raster tile 16x16 -> 32x32. Halo redundancy (each CTA fully
// re-processes gaussians whose footprint crosses its border) drops from
// (22/16)^2 = 1.89x to (38/32)^2 = 1.41x -> ~25% less candidate-scan /
// MUFU / load work chip-wide at a ~7% wave-imbalance cost.
// Fixed shapes: B=4, inp 3x128x128, scale=2, grid 256x256 gaussians/batch,
// image 4x3x256x256 fp32 output.
// ---------------------------------------------------------------------------

#define BATCH   4
#define INH     128
#define INW     128
#define GH      256
#define GW      256
#define IMH     256
#define IMW     256
#define NGAUSS  (GH * GW)

#define TW      32
#define TH      32
#define RSX     38      // gx in [tx0-2, tx0+TW+3] -> TW+6
#define RSY     38

__device__ __forceinline__ float tanh_approx(float x) {
    float r;
    asm("tanh.approx.f32 %0, %1;" : "=f"(r) : "f"(x));
    return r;
}

// Scratch (allocation-free contract: __device__ globals)
__device__ float  g_weff[4 * 27 * 24];          // [uv][t][o], o contiguous
__device__ float  g_beff[4 * 24];               // [uv][o]
__device__ float2 g_center[BATCH * NGAUSS];     // (cx, cy)
__device__ float4 g_color [BATCH * NGAUSS];     // (r, g, b, pad)

// ---------------------------------------------------------------------------
// Kernel 0: weight fold (v9 - measured floor ~6us across 5 variants).
// ---------------------------------------------------------------------------
__global__ void __launch_bounds__(512) fold_kernel(
    const float* __restrict__ w_enc,   // (1024, 3, 3, 3) -> [C*27 + t]
    const float* __restrict__ b_enc,   // (1024,)
    const float* __restrict__ w_head,  // (24, 256)
    const float* __restrict__ b_head)  // (24,)
{
    __shared__ float red[16][28];

    int uv = blockIdx.x / 24;          // grid 96
    int o  = blockIdx.x - uv * 24;
    int u = uv >> 1, v = uv & 1;

    int warp = threadIdx.x >> 5;
    int lane = threadIdx.x & 31;

    if (lane < 28) {
        float acc = 0.f;
        #pragma unroll
        for (int i = 0; i < 16; i++) {
            int ch = warp * 16 + i;
            int c = ch >> 2, a = (ch >> 1) & 1, e = ch & 1;
            int C = c * 16 + (2 * u + a) * 4 + (2 * v + e);
            float wh = __ldg(w_head + o * 256 + ch);           // warp-uniform
            float x  = (lane < 27) ? __ldg(w_enc + C * 27 + lane)
                                   : __ldg(b_enc + C);
            acc = fmaf(wh, x, acc);
        }
        red[warp][lane] = acc;
    }
    __syncthreads();

    if (threadIdx.x < 28) {
        int t = threadIdx.x;
        float s = 0.f;
        #pragma unroll
        for (int w = 0; w < 16; w++) s += red[w][t];
        if (t < 27) g_weff[uv * 648 + t * 24 + o] = s;
        else        g_beff[uv * 24 + o] = s + b_head[o];
    }
}

// ---------------------------------------------------------------------------
// Kernel 1: predict (frozen compute, R4 config + PDL). 1024 CTAs x 64 thr.
// ---------------------------------------------------------------------------
__global__ void __launch_bounds__(64) predict_kernel(const float* __restrict__ inp)
{
    __shared__ __align__(16) float sW[4 * 648];      // [uv][t][o]
    __shared__ float sB[4 * 24];

    int idx = blockIdx.x * 64 + threadIdx.x;    // 0..65535
    int b   = idx >> 14;
    int rem = idx & 16383;
    int i   = rem >> 7;
    int j   = rem & 127;

    // Patch loads first - independent of fold's output (PDL overlap).
    float patch[27];
    const float* ib = inp + (size_t)b * 3 * INH * INW;
    #pragma unroll
    for (int ic = 0; ic < 3; ic++) {
        #pragma unroll
        for (int ky = 0; ky < 3; ky++) {
            int y = i + ky - 1;
            #pragma unroll
            for (int kx = 0; kx < 3; kx++) {
                int x = j + kx - 1;
                float vv = 0.f;
                if ((unsigned)y < INH && (unsigned)x < INW)
                    vv = __ldg(ib + ic * INH * INW + y * INW + x);
                patch[ic * 9 + ky * 3 + kx] = vv;
            }
        }
    }

    cudaGridDependencySynchronize();

    for (int t = threadIdx.x; t < 4 * 648; t += 64) sW[t] = g_weff[t];
    for (int t = threadIdx.x; t < 96; t += 64) sB[t] = g_beff[t];
    __syncthreads();

    #pragma unroll
    for (int uv = 0; uv < 4; uv++) {
        float acc[24];
        #pragma unroll
        for (int o = 0; o < 24; o++) acc[o] = sB[uv * 24 + o];

        const float4* wrow = (const float4*)(sW + uv * 648);
        #pragma unroll
        for (int t = 0; t < 27; t++) {
            float xv = patch[t];
            #pragma unroll
            for (int q = 0; q < 6; q++) {
                float4 wv = wrow[t * 6 + q];
                acc[q * 4 + 0] = fmaf(wv.x, xv, acc[q * 4 + 0]);
                acc[q * 4 + 1] = fmaf(wv.y, xv, acc[q * 4 + 1]);
                acc[q * 4 + 2] = fmaf(wv.z, xv, acc[q * 4 + 2]);
                acc[q * 4 + 3] = fmaf(wv.w, xv, acc[q * 4 + 3]);
            }
        }

        float lg0 = acc[5], lg1 = acc[11], lg2 = acc[17], lg3 = acc[23];
        float m = fmaxf(fmaxf(lg0, lg1), fmaxf(lg2, lg3));
        float w0 = __expf(lg0 - m), w1 = __expf(lg1 - m);
        float w2 = __expf(lg2 - m), w3 = __expf(lg3 - m);
        float inv = 1.f / (w0 + w1 + w2 + w3);

        float r = 0.f, g = 0.f, bl = 0.f, ox = 0.f, oy = 0.f;
        #pragma unroll
        for (int k = 0; k < 4; k++) {
            float wk = ((k == 0) ? w0 : (k == 1) ? w1 : (k == 2) ? w2 : w3) * inv;
            r  = fmaf(acc[k * 6 + 0], wk, r);
            g  = fmaf(acc[k * 6 + 1], wk, g);
            bl = fmaf(acc[k * 6 + 2], wk, bl);
            ox = fmaf(tanh_approx(acc[k * 6 + 3]), wk, ox);
            oy = fmaf(tanh_approx(acc[k * 6 + 4]), wk, oy);
        }

        int u = uv >> 1, v = uv & 1;
        int gy = 2 * i + u, gx = 2 * j + v;
        float cx = (float)gx + 2.f * ox - 1.f;
        float cy = (float)gy + 2.f * oy - 1.f;

        int gidx = b * NGAUSS + gy * GW + gx;
        g_center[gidx] = make_float2(cx, cy);
        g_color[gidx]  = make_float4(r, g, bl, 0.f);
    }
}

// ---------------------------------------------------------------------------
// Kernel 2: rasterize, scatter. One CTA per 32x32 tile per batch (256 CTAs).
// Interleaved acc[3p+ch] (bank fix); 4x4 effective footprint; 38x38 halo;
// stride-7 lane permutation (coprime to 38, adjacent lanes 7 apart so 4-wide
// footprints stay disjoint). PDL: smem zeroing before griddepsync.
// ---------------------------------------------------------------------------
__global__ void __launch_bounds__(256) raster_kernel(float* __restrict__ out)
{
    __shared__ float acc[3 * TH * TW];  // interleaved [p][ch], 12 KB

    int tx0 = (blockIdx.x & 7) * TW;
    int ty0 = (blockIdx.x >> 3) * TH;
    int b   = blockIdx.y;

    for (int p = threadIdx.x; p < 3 * TH * TW; p += 256) acc[p] = 0.f;

    cudaGridDependencySynchronize();
    __syncthreads();

    const float2* ctr = g_center + b * NGAUSS;
    const float4* col = g_color  + b * NGAUSS;

    for (int idx = threadIdx.x; idx < RSX * RSY; idx += 256) {
        int ry = idx / RSX;
        int j  = idx - ry * RSX;
        int rx = (j * 7) % RSX;             // de-conflict permutation
        int gy = ty0 - 2 + ry;
        int gx = tx0 - 2 + rx;
        if ((unsigned)gy >= GH || (unsigned)gx >= GW) continue;

        int gi = gy * GW + gx;
        float2 c = ctr[gi];

        float ixf = floorf(c.x);
        float iyf = floorf(c.y);

        int txl = (int)ixf - 1 - tx0;
        int tyl = (int)iyf - 1 - ty0;
        if (txl >= TW || txl <= -4 || tyl >= TH || tyl <= -4) continue;

        float4 rgbv = col[gi];

        float ex[4], ey[4];
        #pragma unroll
        for (int o = 0; o < 4; o++) {
            float dx = ixf + (float)(o - 1) - c.x;
            float dy = iyf + (float)(o - 1) - c.y;
            ex[o] = __expf(-2.f * dx * dx);
            ey[o] = __expf(-2.f * dy * dy);
        }

        #pragma unroll
        for (int oy = 0; oy < 4; oy++) {
            int ty = tyl + oy;
            if ((unsigned)ty >= TH) continue;
            float eyv = ey[oy];
            #pragma unroll
            for (int ox = 0; ox < 4; ox++) {
                int tx = txl + ox;
                if ((unsigned)tx >= TW) continue;
                float a = fminf(eyv * ex[ox], 0.999f);
                if (a > (1.0f / 255.0f)) {
                    int p3 = (ty * TW + tx) * 3;
                    atomicAdd(&acc[p3 + 0], a * rgbv.x);
                    atomicAdd(&acc[p3 + 1], a * rgbv.y);
                    atomicAdd(&acc[p3 + 2], a * rgbv.z);
                }
            }
        }
    }
    __syncthreads();

    float* ob = out + (size_t)b * 3 * IMH * IMW;
    for (int p = threadIdx.x; p < TH * TW; p += 256) {
        int ty = p >> 5;          // TW = 32
        int tx = p & 31;
        int o  = (ty0 + ty) * IMW + (tx0 + tx);
        #pragma unroll
        for (int ch = 0; ch < 3; ch++) {
            float vv = acc[p * 3 + ch];
            ob[ch * IMH * IMW + o] = fminf(fmaxf(vv, 0.f), 1.f);
        }
    }
}

// ---------------------------------------------------------------------------
// Launch: fold -> predict -> raster, one stream, PDL on the two successors.
// No streams/events/allocations. Inputs: inp, w_enc, b_enc, w_head, b_head.
// ---------------------------------------------------------------------------
extern "C" void kernel_launch(void* const* d_in, const int* in_sizes, int n_in,
                              void* d_out, int out_size)
{
    const float* inp    = (const float*)d_in[0];
    const float* w_enc  = (const float*)d_in[1];
    const float* b_enc  = (const float*)d_in[2];
    const float* w_head = (const float*)d_in[3];
    const float* b_head = (const float*)d_in[4];
    float* out = (float*)d_out;

    fold_kernel<<<96, 512>>>(w_enc, b_enc, w_head, b_head);

    cudaLaunchAttribute pdl[1];
    pdl[0].id = cudaLaunchAttributeProgrammaticStreamSerialization;
    pdl[0].val.programmaticStreamSerializationAllowed = 1;

    {
        cudaLaunchConfig_t cfg = {};
        cfg.gridDim  = dim3(1024);
        cfg.blockDim = dim3(64);
        cfg.attrs    = pdl;
        cfg.numAttrs = 1;
        if (cudaLaunchKernelEx(&cfg, predict_kernel, inp) != cudaSuccess)
            predict_kernel<<<1024, 64>>>(inp);
    }
    {
        cudaLaunchConfig_t cfg = {};
        cfg.gridDim  = dim3(64, BATCH);
        cfg.blockDim = dim3(256);
        cfg.attrs    = pdl;
        cfg.numAttrs = 1;
        if (cudaLaunchKernelEx(&cfg, raster_kernel, out) != cudaSuccess)
            raster_kernel<<<dim3(64, BATCH), 256>>>(out);
    }
}

// round 14
// speedup vs baseline: 1.1719x; 1.1719x over previous
#include <cuda_runtime.h>
#include <math.h>

// ---------------------------------------------------------------------------
// GRAPEIso: conv3x3(3->1024) + pixel_shuffle(4) + pixel_unshuffle(2) + head
// algebraically folded into a 96-output 3x3 conv, then Gaussian splatting
// with exclusive shared-memory image tiles (scatter + smem atomics).
// R14: raster geometry reverted to 16x16 (32x32 measured -10us: wave
// quantization of fat CTAs). NEW: per-gaussian exp tables (ex[4], ey[4])
// and integer anchor (ix,iy) computed ONCE in predict (idle MUFU pipe)
// instead of per tile-visit in raster (1.89x halo redundancy). Raster's
// inner loop is now load + FMUL + fmin + smem-atomic only.
// Fixed shapes: B=4, inp 3x128x128, scale=2, grid 256x256 gaussians/batch,
// image 4x3x256x256 fp32 output.
// ---------------------------------------------------------------------------

#define BATCH   4
#define INH     128
#define INW     128
#define GH      256
#define GW      256
#define IMH     256
#define IMW     256
#define NGAUSS  (GH * GW)

#define TW      16
#define TH      16
#define RSX     22
#define RSY     22

__device__ __forceinline__ float tanh_approx(float x) {
    float r;
    asm("tanh.approx.f32 %0, %1;" : "=f"(r) : "f"(x));
    return r;
}

// Scratch (allocation-free contract: __device__ globals)
__device__ float  g_weff[4 * 27 * 24];          // [uv][t][o], o contiguous
__device__ float  g_beff[4 * 24];               // [uv][o]
__device__ int2   g_ipos [BATCH * NGAUSS];      // (ix, iy) = floor(center)
__device__ float4 g_ex   [BATCH * NGAUSS];      // exp(-2 dx^2), dx at ix-1..ix+2
__device__ float4 g_ey   [BATCH * NGAUSS];      // exp(-2 dy^2)
__device__ float4 g_color[BATCH * NGAUSS];      // (r, g, b, pad)

// ---------------------------------------------------------------------------
// Kernel 0: weight fold (v9 - measured floor ~6us across 5 variants).
// ---------------------------------------------------------------------------
__global__ void __launch_bounds__(512) fold_kernel(
    const float* __restrict__ w_enc,   // (1024, 3, 3, 3) -> [C*27 + t]
    const float* __restrict__ b_enc,   // (1024,)
    const float* __restrict__ w_head,  // (24, 256)
    const float* __restrict__ b_head)  // (24,)
{
    __shared__ float red[16][28];

    int uv = blockIdx.x / 24;          // grid 96
    int o  = blockIdx.x - uv * 24;
    int u = uv >> 1, v = uv & 1;

    int warp = threadIdx.x >> 5;
    int lane = threadIdx.x & 31;

    if (lane < 28) {
        float acc = 0.f;
        #pragma unroll
        for (int i = 0; i < 16; i++) {
            int ch = warp * 16 + i;
            int c = ch >> 2, a = (ch >> 1) & 1, e = ch & 1;
            int C = c * 16 + (2 * u + a) * 4 + (2 * v + e);
            float wh = __ldg(w_head + o * 256 + ch);           // warp-uniform
            float x  = (lane < 27) ? __ldg(w_enc + C * 27 + lane)
                                   : __ldg(b_enc + C);
            acc = fmaf(wh, x, acc);
        }
        red[warp][lane] = acc;
    }
    __syncthreads();

    if (threadIdx.x < 28) {
        int t = threadIdx.x;
        float s = 0.f;
        #pragma unroll
        for (int w = 0; w < 16; w++) s += red[w][t];
        if (t < 27) g_weff[uv * 648 + t * 24 + o] = s;
        else        g_beff[uv * 24 + o] = s + b_head[o];
    }
}

// ---------------------------------------------------------------------------
// Kernel 1: predict. Frozen mainloop (R4 config); epilogue now also emits
// the per-gaussian splat tables: anchor (ix,iy) and separable exp factors
// ex[4], ey[4] at offsets {-1,0,1,2} around the anchor. PDL preamble.
// ---------------------------------------------------------------------------
__global__ void __launch_bounds__(64) predict_kernel(const float* __restrict__ inp)
{
    __shared__ __align__(16) float sW[4 * 648];      // [uv][t][o]
    __shared__ float sB[4 * 24];

    int idx = blockIdx.x * 64 + threadIdx.x;    // 0..65535
    int b   = idx >> 14;
    int rem = idx & 16383;
    int i   = rem >> 7;
    int j   = rem & 127;

    // Patch loads first - independent of fold's output (PDL overlap).
    float patch[27];
    const float* ib = inp + (size_t)b * 3 * INH * INW;
    #pragma unroll
    for (int ic = 0; ic < 3; ic++) {
        #pragma unroll
        for (int ky = 0; ky < 3; ky++) {
            int y = i + ky - 1;
            #pragma unroll
            for (int kx = 0; kx < 3; kx++) {
                int x = j + kx - 1;
                float vv = 0.f;
                if ((unsigned)y < INH && (unsigned)x < INW)
                    vv = __ldg(ib + ic * INH * INW + y * INW + x);
                patch[ic * 9 + ky * 3 + kx] = vv;
            }
        }
    }

    cudaGridDependencySynchronize();

    for (int t = threadIdx.x; t < 4 * 648; t += 64) sW[t] = g_weff[t];
    for (int t = threadIdx.x; t < 96; t += 64) sB[t] = g_beff[t];
    __syncthreads();

    #pragma unroll
    for (int uv = 0; uv < 4; uv++) {
        float acc[24];
        #pragma unroll
        for (int o = 0; o < 24; o++) acc[o] = sB[uv * 24 + o];

        const float4* wrow = (const float4*)(sW + uv * 648);
        #pragma unroll
        for (int t = 0; t < 27; t++) {
            float xv = patch[t];
            #pragma unroll
            for (int q = 0; q < 6; q++) {
                float4 wv = wrow[t * 6 + q];
                acc[q * 4 + 0] = fmaf(wv.x, xv, acc[q * 4 + 0]);
                acc[q * 4 + 1] = fmaf(wv.y, xv, acc[q * 4 + 1]);
                acc[q * 4 + 2] = fmaf(wv.z, xv, acc[q * 4 + 2]);
                acc[q * 4 + 3] = fmaf(wv.w, xv, acc[q * 4 + 3]);
            }
        }

        float lg0 = acc[5], lg1 = acc[11], lg2 = acc[17], lg3 = acc[23];
        float m = fmaxf(fmaxf(lg0, lg1), fmaxf(lg2, lg3));
        float w0 = __expf(lg0 - m), w1 = __expf(lg1 - m);
        float w2 = __expf(lg2 - m), w3 = __expf(lg3 - m);
        float inv = 1.f / (w0 + w1 + w2 + w3);

        float r = 0.f, g = 0.f, bl = 0.f, ox = 0.f, oy = 0.f;
        #pragma unroll
        for (int k = 0; k < 4; k++) {
            float wk = ((k == 0) ? w0 : (k == 1) ? w1 : (k == 2) ? w2 : w3) * inv;
            r  = fmaf(acc[k * 6 + 0], wk, r);
            g  = fmaf(acc[k * 6 + 1], wk, g);
            bl = fmaf(acc[k * 6 + 2], wk, bl);
            ox = fmaf(tanh_approx(acc[k * 6 + 3]), wk, ox);
            oy = fmaf(tanh_approx(acc[k * 6 + 4]), wk, oy);
        }

        int u = uv >> 1, v = uv & 1;
        int gy = 2 * i + u, gx = 2 * j + v;
        float cx = (float)gx + 2.f * ox - 1.f;
        float cy = (float)gy + 2.f * oy - 1.f;

        // Splat tables: anchor + separable exp factors (once per gaussian;
        // raster previously recomputed these per tile-visit x1.89 halo).
        float ixf = floorf(cx);
        float iyf = floorf(cy);
        float exv[4], eyv[4];
        #pragma unroll
        for (int o = 0; o < 4; o++) {
            float dx = ixf + (float)(o - 1) - cx;
            float dy = iyf + (float)(o - 1) - cy;
            exv[o] = __expf(-2.f * dx * dx);
            eyv[o] = __expf(-2.f * dy * dy);
        }

        int gidx = b * NGAUSS + gy * GW + gx;
        g_ipos [gidx] = make_int2((int)ixf, (int)iyf);
        g_ex   [gidx] = make_float4(exv[0], exv[1], exv[2], exv[3]);
        g_ey   [gidx] = make_float4(eyv[0], eyv[1], eyv[2], eyv[3]);
        g_color[gidx] = make_float4(r, g, bl, 0.f);
    }
}

// ---------------------------------------------------------------------------
// Kernel 2: rasterize, scatter, 16x16 tiles (R12 geometry - the best).
// Per visit: 8B anchor load -> bbox reject -> three 16B vector loads ->
// FMUL/fmin/cmp + smem atomics. Zero MUFU, zero floor. Interleaved
// acc[3p+ch]; stride-5 permutation; PDL preamble.
// ---------------------------------------------------------------------------
__global__ void __launch_bounds__(256) raster_kernel(float* __restrict__ out)
{
    __shared__ float acc[3 * TH * TW];  // interleaved [p][ch]

    int tx0 = (blockIdx.x & 15) * TW;
    int ty0 = (blockIdx.x >> 4) * TH;
    int b   = blockIdx.y;

    for (int p = threadIdx.x; p < 3 * TH * TW; p += 256) acc[p] = 0.f;

    cudaGridDependencySynchronize();
    __syncthreads();

    const int2*   ipos = g_ipos  + b * NGAUSS;
    const float4* gex  = g_ex    + b * NGAUSS;
    const float4* gey  = g_ey    + b * NGAUSS;
    const float4* col  = g_color + b * NGAUSS;

    for (int idx = threadIdx.x; idx < RSX * RSY; idx += 256) {
        int ry = idx / RSX;
        int j  = idx - ry * RSX;
        int rx = (j * 5) % RSX;             // de-conflict permutation
        int gy = ty0 - 2 + ry;
        int gx = tx0 - 2 + rx;
        if ((unsigned)gy >= GH || (unsigned)gx >= GW) continue;

        int gi = gy * GW + gx;
        int2 ip = ipos[gi];

        int txl = ip.x - 1 - tx0;
        int tyl = ip.y - 1 - ty0;
        if (txl >= TW || txl <= -4 || tyl >= TH || tyl <= -4) continue;

        float4 ex4  = gex[gi];
        float4 ey4  = gey[gi];
        float4 rgbv = col[gi];
        float ex[4] = {ex4.x, ex4.y, ex4.z, ex4.w};
        float ey[4] = {ey4.x, ey4.y, ey4.z, ey4.w};

        #pragma unroll
        for (int oy = 0; oy < 4; oy++) {
            int ty = tyl + oy;
            if ((unsigned)ty >= TH) continue;
            float eyv = ey[oy];
            #pragma unroll
            for (int ox = 0; ox < 4; ox++) {
                int tx = txl + ox;
                if ((unsigned)tx >= TW) continue;
                float a = fminf(eyv * ex[ox], 0.999f);
                if (a > (1.0f / 255.0f)) {
                    int p3 = (ty * TW + tx) * 3;
                    atomicAdd(&acc[p3 + 0], a * rgbv.x);
                    atomicAdd(&acc[p3 + 1], a * rgbv.y);
                    atomicAdd(&acc[p3 + 2], a * rgbv.z);
                }
            }
        }
    }
    __syncthreads();

    float* ob = out + (size_t)b * 3 * IMH * IMW;
    for (int p = threadIdx.x; p < TH * TW; p += 256) {
        int ty = p >> 4;
        int tx = p & 15;
        int o  = (ty0 + ty) * IMW + (tx0 + tx);
        #pragma unroll
        for (int ch = 0; ch < 3; ch++) {
            float vv = acc[p * 3 + ch];
            ob[ch * IMH * IMW + o] = fminf(fmaxf(vv, 0.f), 1.f);
        }
    }
}

// ---------------------------------------------------------------------------
// Launch: fold -> predict -> raster, one stream, PDL on the two successors.
// No streams/events/allocations. Inputs: inp, w_enc, b_enc, w_head, b_head.
// ---------------------------------------------------------------------------
extern "C" void kernel_launch(void* const* d_in, const int* in_sizes, int n_in,
                              void* d_out, int out_size)
{
    const float* inp    = (const float*)d_in[0];
    const float* w_enc  = (const float*)d_in[1];
    const float* b_enc  = (const float*)d_in[2];
    const float* w_head = (const float*)d_in[3];
    const float* b_head = (const float*)d_in[4];
    float* out = (float*)d_out;

    fold_kernel<<<96, 512>>>(w_enc, b_enc, w_head, b_head);

    cudaLaunchAttribute pdl[1];
    pdl[0].id = cudaLaunchAttributeProgrammaticStreamSerialization;
    pdl[0].val.programmaticStreamSerializationAllowed = 1;

    {
        cudaLaunchConfig_t cfg = {};
        cfg.gridDim  = dim3(1024);
        cfg.blockDim = dim3(64);
        cfg.attrs    = pdl;
        cfg.numAttrs = 1;
        if (cudaLaunchKernelEx(&cfg, predict_kernel, inp) != cudaSuccess)
            predict_kernel<<<1024, 64>>>(inp);
    }
    {
        cudaLaunchConfig_t cfg = {};
        cfg.gridDim  = dim3(256, BATCH);
        cfg.blockDim = dim3(256);
        cfg.attrs    = pdl;
        cfg.numAttrs = 1;
        if (cudaLaunchKernelEx(&cfg, raster_kernel, out) != cudaSuccess)
            raster_kernel<<<dim3(256, BATCH), 256>>>(out);
    }
}

// round 15
// speedup vs baseline: 1.2919x; 1.1024x over previous
#include <cuda_runtime.h>
#include <math.h>

// ---------------------------------------------------------------------------
// GRAPEIso: conv3x3(3->1024) + pixel_shuffle(4) + pixel_unshuffle(2) + head
// algebraically folded into a 96-output 3x3 conv, then Gaussian splatting
// with exclusive shared-memory image tiles (scatter + smem atomics).
// R15 = exact R12 config (the 41.2us best: fold-v9, 16x16 scatter raster
// with interleaved acc + stride-5 permutation, PDL) with ONE change:
// predict's inner loop uses packed fma.rn.f32x2 (FFMA2), patch packed at
// load time so no scalar/packed double-array register blowup (the R3 bug),
// CTA shape and staging untouched (the R5 confound).
// Fixed shapes: B=4, inp 3x128x128, scale=2, grid 256x256 gaussians/batch,
// image 4x3x256x256 fp32 output.
// ---------------------------------------------------------------------------

#define BATCH   4
#define INH     128
#define INW     128
#define GH      256
#define GW      256
#define IMH     256
#define IMW     256
#define NGAUSS  (GH * GW)

#define TW      16
#define TH      16
#define RSX     22
#define RSY     22

typedef unsigned long long ull;

#define FMA_F32X2(acc, a, b) \
    asm("fma.rn.f32x2 %0, %1, %2, %0;" : "+l"(acc) : "l"(a), "l"(b))
#define PACK_F32X2(out, lo, hi) \
    asm("mov.b64 %0, {%1, %2};" : "=l"(out) : "f"(lo), "f"(hi))
#define UNPACK_F32X2(lo, hi, in) \
    asm("mov.b64 {%0, %1}, %2;" : "=f"(lo), "=f"(hi) : "l"(in))

__device__ __forceinline__ float tanh_approx(float x) {
    float r;
    asm("tanh.approx.f32 %0, %1;" : "=f"(r) : "f"(x));
    return r;
}

// Scratch (allocation-free contract: __device__ globals)
__device__ float  g_weff[4 * 27 * 24];          // [uv][t][o], o contiguous
__device__ float  g_beff[4 * 24];               // [uv][o]
__device__ float2 g_center[BATCH * NGAUSS];     // (cx, cy)
__device__ float4 g_color [BATCH * NGAUSS];     // (r, g, b, pad)

// ---------------------------------------------------------------------------
// Kernel 0: weight fold (v9 - measured floor ~6us across 5 variants).
// ---------------------------------------------------------------------------
__global__ void __launch_bounds__(512) fold_kernel(
    const float* __restrict__ w_enc,   // (1024, 3, 3, 3) -> [C*27 + t]
    const float* __restrict__ b_enc,   // (1024,)
    const float* __restrict__ w_head,  // (24, 256)
    const float* __restrict__ b_head)  // (24,)
{
    __shared__ float red[16][28];

    int uv = blockIdx.x / 24;          // grid 96
    int o  = blockIdx.x - uv * 24;
    int u = uv >> 1, v = uv & 1;

    int warp = threadIdx.x >> 5;
    int lane = threadIdx.x & 31;

    if (lane < 28) {
        float acc = 0.f;
        #pragma unroll
        for (int i = 0; i < 16; i++) {
            int ch = warp * 16 + i;
            int c = ch >> 2, a = (ch >> 1) & 1, e = ch & 1;
            int C = c * 16 + (2 * u + a) * 4 + (2 * v + e);
            float wh = __ldg(w_head + o * 256 + ch);           // warp-uniform
            float x  = (lane < 27) ? __ldg(w_enc + C * 27 + lane)
                                   : __ldg(b_enc + C);
            acc = fmaf(wh, x, acc);
        }
        red[warp][lane] = acc;
    }
    __syncthreads();

    if (threadIdx.x < 28) {
        int t = threadIdx.x;
        float s = 0.f;
        #pragma unroll
        for (int w = 0; w < 16; w++) s += red[w][t];
        if (t < 27) g_weff[uv * 648 + t * 24 + o] = s;
        else        g_beff[uv * 24 + o] = s + b_head[o];
    }
}

// ---------------------------------------------------------------------------
// Kernel 1: predict. 1024 CTAs x 64 threads, PDL preamble (patch loads
// before griddepsync). Inner loop: packed f32x2 FFMA - 1296 FFMA2 instead
// of 2592 FFMA per thread. Patch is packed AT LOAD TIME (scalar value is
// a transient, never an array) so register count stays ~110.
// ---------------------------------------------------------------------------
__global__ void __launch_bounds__(64) predict_kernel(const float* __restrict__ inp)
{
    __shared__ __align__(16) float sW[4 * 648];      // [uv][t][o]
    __shared__ __align__(16) float sB[4 * 24];

    int idx = blockIdx.x * 64 + threadIdx.x;    // 0..65535
    int b   = idx >> 14;
    int rem = idx & 16383;
    int i   = rem >> 7;
    int j   = rem & 127;

    // Patch loads first (independent of fold - PDL overlap), packed (x,x).
    ull patch2[27];
    const float* ib = inp + (size_t)b * 3 * INH * INW;
    #pragma unroll
    for (int ic = 0; ic < 3; ic++) {
        #pragma unroll
        for (int ky = 0; ky < 3; ky++) {
            int y = i + ky - 1;
            #pragma unroll
            for (int kx = 0; kx < 3; kx++) {
                int x = j + kx - 1;
                float vv = 0.f;
                if ((unsigned)y < INH && (unsigned)x < INW)
                    vv = __ldg(ib + ic * INH * INW + y * INW + x);
                PACK_F32X2(patch2[ic * 9 + ky * 3 + kx], vv, vv);
            }
        }
    }

    cudaGridDependencySynchronize();

    for (int t = threadIdx.x; t < 4 * 648; t += 64) sW[t] = g_weff[t];
    for (int t = threadIdx.x; t < 96; t += 64) sB[t] = g_beff[t];
    __syncthreads();

    #pragma unroll
    for (int uv = 0; uv < 4; uv++) {
        // 24 accumulators as 12 packed f32x2, initialized straight from
        // smem bias pairs (LDS.64).
        ull acc2[12];
        const ull* sB2 = (const ull*)(sB + uv * 24);
        #pragma unroll
        for (int q = 0; q < 12; q++) acc2[q] = sB2[q];

        const ulonglong2* wrow = (const ulonglong2*)(sW + uv * 648);
        #pragma unroll
        for (int t = 0; t < 27; t++) {
            ull xv2 = patch2[t];
            #pragma unroll
            for (int q = 0; q < 6; q++) {
                ulonglong2 w2 = wrow[t * 6 + q];     // 4 weights = 2 f32x2
                FMA_F32X2(acc2[2 * q],     w2.x, xv2);
                FMA_F32X2(acc2[2 * q + 1], w2.y, xv2);
            }
        }

        float acc[24];
        #pragma unroll
        for (int q = 0; q < 12; q++)
            UNPACK_F32X2(acc[2 * q], acc[2 * q + 1], acc2[q]);

        float lg0 = acc[5], lg1 = acc[11], lg2 = acc[17], lg3 = acc[23];
        float m = fmaxf(fmaxf(lg0, lg1), fmaxf(lg2, lg3));
        float w0 = __expf(lg0 - m), w1 = __expf(lg1 - m);
        float w2 = __expf(lg2 - m), w3 = __expf(lg3 - m);
        float inv = 1.f / (w0 + w1 + w2 + w3);

        float r = 0.f, g = 0.f, bl = 0.f, ox = 0.f, oy = 0.f;
        #pragma unroll
        for (int k = 0; k < 4; k++) {
            float wk = ((k == 0) ? w0 : (k == 1) ? w1 : (k == 2) ? w2 : w3) * inv;
            r  = fmaf(acc[k * 6 + 0], wk, r);
            g  = fmaf(acc[k * 6 + 1], wk, g);
            bl = fmaf(acc[k * 6 + 2], wk, bl);
            ox = fmaf(tanh_approx(acc[k * 6 + 3]), wk, ox);
            oy = fmaf(tanh_approx(acc[k * 6 + 4]), wk, oy);
        }

        int u = uv >> 1, v = uv & 1;
        int gy = 2 * i + u, gx = 2 * j + v;
        float cx = (float)gx + 2.f * ox - 1.f;
        float cy = (float)gy + 2.f * oy - 1.f;

        int gidx = b * NGAUSS + gy * GW + gx;
        g_center[gidx] = make_float2(cx, cy);
        g_color[gidx]  = make_float4(r, g, bl, 0.f);
    }
}

// ---------------------------------------------------------------------------
// Kernel 2: rasterize (exact R12 - the measured best). One CTA per 16x16
// tile per batch; interleaved acc[3p+ch]; 4x4 effective footprint; 22x22
// halo; stride-5 lane permutation; PDL: smem zeroing before griddepsync.
// ---------------------------------------------------------------------------
__global__ void __launch_bounds__(256) raster_kernel(float* __restrict__ out)
{
    __shared__ float acc[3 * TH * TW];  // interleaved [p][ch]

    int tx0 = (blockIdx.x & 15) * TW;
    int ty0 = (blockIdx.x >> 4) * TH;
    int b   = blockIdx.y;

    for (int p = threadIdx.x; p < 3 * TH * TW; p += 256) acc[p] = 0.f;

    cudaGridDependencySynchronize();
    __syncthreads();

    const float2* ctr = g_center + b * NGAUSS;
    const float4* col = g_color  + b * NGAUSS;

    for (int idx = threadIdx.x; idx < RSX * RSY; idx += 256) {
        int ry = idx / RSX;
        int j  = idx - ry * RSX;
        int rx = (j * 5) % RSX;             // de-conflict permutation
        int gy = ty0 - 2 + ry;
        int gx = tx0 - 2 + rx;
        if ((unsigned)gy >= GH || (unsigned)gx >= GW) continue;

        int gi = gy * GW + gx;
        float2 c = ctr[gi];

        float ixf = floorf(c.x);
        float iyf = floorf(c.y);

        int txl = (int)ixf - 1 - tx0;
        int tyl = (int)iyf - 1 - ty0;
        if (txl >= TW || txl <= -4 || tyl >= TH || tyl <= -4) continue;

        float4 rgbv = col[gi];

        float ex[4], ey[4];
        #pragma unroll
        for (int o = 0; o < 4; o++) {
            float dx = ixf + (float)(o - 1) - c.x;
            float dy = iyf + (float)(o - 1) - c.y;
            ex[o] = __expf(-2.f * dx * dx);
            ey[o] = __expf(-2.f * dy * dy);
        }

        #pragma unroll
        for (int oy = 0; oy < 4; oy++) {
            int ty = tyl + oy;
            if ((unsigned)ty >= TH) continue;
            float eyv = ey[oy];
            #pragma unroll
            for (int ox = 0; ox < 4; ox++) {
                int tx = txl + ox;
                if ((unsigned)tx >= TW) continue;
                float a = fminf(eyv * ex[ox], 0.999f);
                if (a > (1.0f / 255.0f)) {
                    int p3 = (ty * TW + tx) * 3;
                    atomicAdd(&acc[p3 + 0], a * rgbv.x);
                    atomicAdd(&acc[p3 + 1], a * rgbv.y);
                    atomicAdd(&acc[p3 + 2], a * rgbv.z);
                }
            }
        }
    }
    __syncthreads();

    float* ob = out + (size_t)b * 3 * IMH * IMW;
    for (int p = threadIdx.x; p < TH * TW; p += 256) {
        int ty = p >> 4;
        int tx = p & 15;
        int o  = (ty0 + ty) * IMW + (tx0 + tx);
        #pragma unroll
        for (int ch = 0; ch < 3; ch++) {
            float vv = acc[p * 3 + ch];
            ob[ch * IMH * IMW + o] = fminf(fmaxf(vv, 0.f), 1.f);
        }
    }
}

// ---------------------------------------------------------------------------
// Launch: fold -> predict -> raster, one stream, PDL on the two successors.
// No streams/events/allocations. Inputs: inp, w_enc, b_enc, w_head, b_head.
// ---------------------------------------------------------------------------
extern "C" void kernel_launch(void* const* d_in, const int* in_sizes, int n_in,
                              void* d_out, int out_size)
{
    const float* inp    = (const float*)d_in[0];
    const float* w_enc  = (const float*)d_in[1];
    const float* b_enc  = (const float*)d_in[2];
    const float* w_head = (const float*)d_in[3];
    const float* b_head = (const float*)d_in[4];
    float* out = (float*)d_out;

    fold_kernel<<<96, 512>>>(w_enc, b_enc, w_head, b_head);

    cudaLaunchAttribute pdl[1];
    pdl[0].id = cudaLaunchAttributeProgrammaticStreamSerialization;
    pdl[0].val.programmaticStreamSerializationAllowed = 1;

    {
        cudaLaunchConfig_t cfg = {};
        cfg.gridDim  = dim3(1024);
        cfg.blockDim = dim3(64);
        cfg.attrs    = pdl;
        cfg.numAttrs = 1;
        if (cudaLaunchKernelEx(&cfg, predict_kernel, inp) != cudaSuccess)
            predict_kernel<<<1024, 64>>>(inp);
    }
    {
        cudaLaunchConfig_t cfg = {};
        cfg.gridDim  = dim3(256, BATCH);
        cfg.blockDim = dim3(256);
        cfg.attrs    = pdl;
        cfg.numAttrs = 1;
        if (cudaLaunchKernelEx(&cfg, raster_kernel, out) != cudaSuccess)
            raster_kernel<<<dim3(256, BATCH), 256>>>(out);
    }
}

// round 16
// speedup vs baseline: 1.3716x; 1.0616x over previous
#include <cuda_runtime.h>
#include <math.h>

// ---------------------------------------------------------------------------
// GRAPEIso: conv3x3(3->1024) + pixel_shuffle(4) + pixel_unshuffle(2) + head
// algebraically folded into a 96-output 3x3 conv, then Gaussian splatting
// with exclusive shared-memory image tiles (scatter + smem atomics).
// R16 = R15 (39.7us: fold-v9, f32x2 predict, 16x16 scatter raster, PDL)
// with: (a) predict T=2 pixel-pairing at 64-thr CTAs - the 648 LDS.128
// weight loads per thread now serve TWO pixels (LDS stream halved; R6's
// T=2 failure was the 32-thr staging overhead, removed here); (b) raster
// inner-2x2 positions skip the alpha-threshold test (provably always
// passes: a >= e^-4 > 1/255).
// Fixed shapes: B=4, inp 3x128x128, scale=2, grid 256x256 gaussians/batch,
// image 4x3x256x256 fp32 output.
// ---------------------------------------------------------------------------

#define BATCH   4
#define INH     128
#define INW     128
#define GH      256
#define GW      256
#define IMH     256
#define IMW     256
#define NGAUSS  (GH * GW)

#define TW      16
#define TH      16
#define RSX     22
#define RSY     22

typedef unsigned long long ull;

#define FMA_F32X2(acc, a, b) \
    asm("fma.rn.f32x2 %0, %1, %2, %0;" : "+l"(acc) : "l"(a), "l"(b))
#define PACK_F32X2(out, lo, hi) \
    asm("mov.b64 %0, {%1, %2};" : "=l"(out) : "f"(lo), "f"(hi))
#define UNPACK_F32X2(lo, hi, in) \
    asm("mov.b64 {%0, %1}, %2;" : "=f"(lo), "=f"(hi) : "l"(in))

__device__ __forceinline__ float tanh_approx(float x) {
    float r;
    asm("tanh.approx.f32 %0, %1;" : "=f"(r) : "f"(x));
    return r;
}

// Scratch (allocation-free contract: __device__ globals)
__device__ float  g_weff[4 * 27 * 24];          // [uv][t][o], o contiguous
__device__ float  g_beff[4 * 24];               // [uv][o]
__device__ float2 g_center[BATCH * NGAUSS];     // (cx, cy)
__device__ float4 g_color [BATCH * NGAUSS];     // (r, g, b, pad)

// ---------------------------------------------------------------------------
// Kernel 0: weight fold (v9 - measured floor ~6-7us across 5 variants).
// ---------------------------------------------------------------------------
__global__ void __launch_bounds__(512) fold_kernel(
    const float* __restrict__ w_enc,   // (1024, 3, 3, 3) -> [C*27 + t]
    const float* __restrict__ b_enc,   // (1024,)
    const float* __restrict__ w_head,  // (24, 256)
    const float* __restrict__ b_head)  // (24,)
{
    __shared__ float red[16][28];

    int uv = blockIdx.x / 24;          // grid 96
    int o  = blockIdx.x - uv * 24;
    int u = uv >> 1, v = uv & 1;

    int warp = threadIdx.x >> 5;
    int lane = threadIdx.x & 31;

    if (lane < 28) {
        float acc = 0.f;
        #pragma unroll
        for (int i = 0; i < 16; i++) {
            int ch = warp * 16 + i;
            int c = ch >> 2, a = (ch >> 1) & 1, e = ch & 1;
            int C = c * 16 + (2 * u + a) * 4 + (2 * v + e);
            float wh = __ldg(w_head + o * 256 + ch);           // warp-uniform
            float x  = (lane < 27) ? __ldg(w_enc + C * 27 + lane)
                                   : __ldg(b_enc + C);
            acc = fmaf(wh, x, acc);
        }
        red[warp][lane] = acc;
    }
    __syncthreads();

    if (threadIdx.x < 28) {
        int t = threadIdx.x;
        float s = 0.f;
        #pragma unroll
        for (int w = 0; w < 16; w++) s += red[w][t];
        if (t < 27) g_weff[uv * 648 + t * 24 + o] = s;
        else        g_beff[uv * 24 + o] = s + b_head[o];
    }
}

// ---------------------------------------------------------------------------
// Predict epilogue: softmax/tanh combine + store one gaussian record.
// ---------------------------------------------------------------------------
__device__ __forceinline__ void emit_gauss(const float* acc, int i, int j,
                                           int uv, int b)
{
    float lg0 = acc[5], lg1 = acc[11], lg2 = acc[17], lg3 = acc[23];
    float m = fmaxf(fmaxf(lg0, lg1), fmaxf(lg2, lg3));
    float w0 = __expf(lg0 - m), w1 = __expf(lg1 - m);
    float w2 = __expf(lg2 - m), w3 = __expf(lg3 - m);
    float inv = 1.f / (w0 + w1 + w2 + w3);

    float r = 0.f, g = 0.f, bl = 0.f, ox = 0.f, oy = 0.f;
    #pragma unroll
    for (int k = 0; k < 4; k++) {
        float wk = ((k == 0) ? w0 : (k == 1) ? w1 : (k == 2) ? w2 : w3) * inv;
        r  = fmaf(acc[k * 6 + 0], wk, r);
        g  = fmaf(acc[k * 6 + 1], wk, g);
        bl = fmaf(acc[k * 6 + 2], wk, bl);
        ox = fmaf(tanh_approx(acc[k * 6 + 3]), wk, ox);
        oy = fmaf(tanh_approx(acc[k * 6 + 4]), wk, oy);
    }

    int u = uv >> 1, v = uv & 1;
    int gy = 2 * i + u, gx = 2 * j + v;
    float cx = (float)gx + 2.f * ox - 1.f;
    float cy = (float)gy + 2.f * oy - 1.f;

    int gidx = b * NGAUSS + gy * GW + gx;
    g_center[gidx] = make_float2(cx, cy);
    g_color[gidx]  = make_float4(r, g, bl, 0.f);
}

// ---------------------------------------------------------------------------
// Kernel 1: predict. 512 CTAs x 64 threads; thread = TWO horizontally
// adjacent pixels (i, 2jp) and (i, 2jp+1). Each weight LDS.128 now feeds
// both pixels' FFMA2 streams. Patch window 3x3x4 packed at load time
// (no scalar double-array). PDL preamble (patch before griddepsync).
// ---------------------------------------------------------------------------
__global__ void __launch_bounds__(64) predict_kernel(const float* __restrict__ inp)
{
    __shared__ __align__(16) float sW[4 * 648];      // [uv][t][o]
    __shared__ __align__(16) float sB[4 * 24];

    int idx = blockIdx.x * 64 + threadIdx.x;    // 0..32767 pixel-pairs
    int b   = idx >> 13;                        // 8192 pairs per batch
    int rem = idx & 8191;
    int i   = rem >> 6;                         // row 0..127
    int j   = (rem & 63) * 2;                   // left pixel col

    // 3x3x4 patch window shared by both pixels, packed (x,x) at load.
    // Index: [(ic*3 + ky)*4 + kx], kx = 0..3 spans cols j-1 .. j+2.
    ull patch2[36];
    const float* ib = inp + (size_t)b * 3 * INH * INW;
    #pragma unroll
    for (int ic = 0; ic < 3; ic++) {
        #pragma unroll
        for (int ky = 0; ky < 3; ky++) {
            int y = i + ky - 1;
            #pragma unroll
            for (int kx = 0; kx < 4; kx++) {
                int x = j + kx - 1;
                float vv = 0.f;
                if ((unsigned)y < INH && (unsigned)x < INW)
                    vv = __ldg(ib + ic * INH * INW + y * INW + x);
                PACK_F32X2(patch2[(ic * 3 + ky) * 4 + kx], vv, vv);
            }
        }
    }

    cudaGridDependencySynchronize();

    for (int t = threadIdx.x; t < 4 * 648; t += 64) sW[t] = g_weff[t];
    for (int t = threadIdx.x; t < 96; t += 64) sB[t] = g_beff[t];
    __syncthreads();

    #pragma unroll
    for (int uv = 0; uv < 4; uv++) {
        ull accA[12], accB[12];
        const ull* sB2 = (const ull*)(sB + uv * 24);
        #pragma unroll
        for (int q = 0; q < 12; q++) { accA[q] = sB2[q]; accB[q] = sB2[q]; }

        const ulonglong2* wrow = (const ulonglong2*)(sW + uv * 648);
        #pragma unroll
        for (int t = 0; t < 27; t++) {
            int ic = t / 9, r9 = t - ic * 9;
            int ky = r9 / 3, kx = r9 - ky * 3;          // compile-time
            ull xa = patch2[(ic * 3 + ky) * 4 + kx];
            ull xb = patch2[(ic * 3 + ky) * 4 + kx + 1];
            #pragma unroll
            for (int q = 0; q < 6; q++) {
                ulonglong2 w2 = wrow[t * 6 + q];         // one LDS, 2 pixels
                FMA_F32X2(accA[2 * q],     w2.x, xa);
                FMA_F32X2(accA[2 * q + 1], w2.y, xa);
                FMA_F32X2(accB[2 * q],     w2.x, xb);
                FMA_F32X2(accB[2 * q + 1], w2.y, xb);
            }
        }

        float fa[24], fb[24];
        #pragma unroll
        for (int q = 0; q < 12; q++) {
            UNPACK_F32X2(fa[2 * q], fa[2 * q + 1], accA[q]);
            UNPACK_F32X2(fb[2 * q], fb[2 * q + 1], accB[q]);
        }
        emit_gauss(fa, i, j,     uv, b);
        emit_gauss(fb, i, j + 1, uv, b);
    }
}

// ---------------------------------------------------------------------------
// Kernel 2: rasterize (R12 geometry). One CTA per 16x16 tile per batch;
// interleaved acc[3p+ch]; 4x4 footprint; 22x22 halo; stride-5 permutation;
// PDL. NEW: inner 2x2 positions (offsets d in {0,1} both axes) skip the
// alpha threshold - provably a >= e^-4 > 1/255 there (compile-time folded).
// ---------------------------------------------------------------------------
__global__ void __launch_bounds__(256) raster_kernel(float* __restrict__ out)
{
    __shared__ float acc[3 * TH * TW];  // interleaved [p][ch]

    int tx0 = (blockIdx.x & 15) * TW;
    int ty0 = (blockIdx.x >> 4) * TH;
    int b   = blockIdx.y;

    for (int p = threadIdx.x; p < 3 * TH * TW; p += 256) acc[p] = 0.f;

    cudaGridDependencySynchronize();
    __syncthreads();

    const float2* ctr = g_center + b * NGAUSS;
    const float4* col = g_color  + b * NGAUSS;

    for (int idx = threadIdx.x; idx < RSX * RSY; idx += 256) {
        int ry = idx / RSX;
        int j  = idx - ry * RSX;
        int rx = (j * 5) % RSX;             // de-conflict permutation
        int gy = ty0 - 2 + ry;
        int gx = tx0 - 2 + rx;
        if ((unsigned)gy >= GH || (unsigned)gx >= GW) continue;

        int gi = gy * GW + gx;
        float2 c = ctr[gi];

        float ixf = floorf(c.x);
        float iyf = floorf(c.y);

        int txl = (int)ixf - 1 - tx0;
        int tyl = (int)iyf - 1 - ty0;
        if (txl >= TW || txl <= -4 || tyl >= TH || tyl <= -4) continue;

        float4 rgbv = col[gi];

        float ex[4], ey[4];
        #pragma unroll
        for (int o = 0; o < 4; o++) {
            float dx = ixf + (float)(o - 1) - c.x;
            float dy = iyf + (float)(o - 1) - c.y;
            ex[o] = __expf(-2.f * dx * dx);
            ey[o] = __expf(-2.f * dy * dy);
        }

        #pragma unroll
        for (int oy = 0; oy < 4; oy++) {
            int ty = tyl + oy;
            if ((unsigned)ty >= TH) continue;
            float eyv = ey[oy];
            #pragma unroll
            for (int ox = 0; ox < 4; ox++) {
                int tx = txl + ox;
                if ((unsigned)tx >= TW) continue;
                float a = fminf(eyv * ex[ox], 0.999f);
                // Inner 2x2 (oy,ox in {1,2}): a >= e^-4 > 1/255 always.
                bool inner = (oy == 1 || oy == 2) && (ox == 1 || ox == 2);
                if (inner || a > (1.0f / 255.0f)) {
                    int p3 = (ty * TW + tx) * 3;
                    atomicAdd(&acc[p3 + 0], a * rgbv.x);
                    atomicAdd(&acc[p3 + 1], a * rgbv.y);
                    atomicAdd(&acc[p3 + 2], a * rgbv.z);
                }
            }
        }
    }
    __syncthreads();

    float* ob = out + (size_t)b * 3 * IMH * IMW;
    for (int p = threadIdx.x; p < TH * TW; p += 256) {
        int ty = p >> 4;
        int tx = p & 15;
        int o  = (ty0 + ty) * IMW + (tx0 + tx);
        #pragma unroll
        for (int ch = 0; ch < 3; ch++) {
            float vv = acc[p * 3 + ch];
            ob[ch * IMH * IMW + o] = fminf(fmaxf(vv, 0.f), 1.f);
        }
    }
}

// ---------------------------------------------------------------------------
// Launch: fold -> predict -> raster, one stream, PDL on the two successors.
// No streams/events/allocations. Inputs: inp, w_enc, b_enc, w_head, b_head.
// ---------------------------------------------------------------------------
extern "C" void kernel_launch(void* const* d_in, const int* in_sizes, int n_in,
                              void* d_out, int out_size)
{
    const float* inp    = (const float*)d_in[0];
    const float* w_enc  = (const float*)d_in[1];
    const float* b_enc  = (const float*)d_in[2];
    const float* w_head = (const float*)d_in[3];
    const float* b_head = (const float*)d_in[4];
    float* out = (float*)d_out;

    fold_kernel<<<96, 512>>>(w_enc, b_enc, w_head, b_head);

    cudaLaunchAttribute pdl[1];
    pdl[0].id = cudaLaunchAttributeProgrammaticStreamSerialization;
    pdl[0].val.programmaticStreamSerializationAllowed = 1;

    {
        cudaLaunchConfig_t cfg = {};
        cfg.gridDim  = dim3(512);
        cfg.blockDim = dim3(64);
        cfg.attrs    = pdl;
        cfg.numAttrs = 1;
        if (cudaLaunchKernelEx(&cfg, predict_kernel, inp) != cudaSuccess)
            predict_kernel<<<512, 64>>>(inp);
    }
    {
        cudaLaunchConfig_t cfg = {};
        cfg.gridDim  = dim3(256, BATCH);
        cfg.blockDim = dim3(256);
        cfg.attrs    = pdl;
        cfg.numAttrs = 1;
        if (cudaLaunchKernelEx(&cfg, raster_kernel, out) != cudaSuccess)
            raster_kernel<<<dim3(256, BATCH), 256>>>(out);
    }
}